// round 1
// baseline (speedup 1.0000x reference)
#include <cuda_runtime.h>
#include <math.h>

// Problem shape (fixed by the dataset): B=32, L=8192, K=64, 20 amino acids.
#define B_DIM 32
#define L_DIM 8192
#define K_DIM 64
#define THREADS 256
#define WARPS (THREADS / 32)
#define TILE_ROWS 128            // rows of i handled per block

__global__ __launch_bounds__(THREADS)
void hp_pairs_kernel(const int* __restrict__ seq,
                     const float* __restrict__ r,
                     const int* __restrict__ j_idx,
                     const float* __restrict__ h,
                     const float* __restrict__ r_half_raw,
                     const float* __restrict__ tau_hp_raw,
                     const int* __restrict__ max_dist,
                     float* __restrict__ out)
{
    __shared__ float s_hseq[L_DIM];   // h[seq[b, :]] for this batch row (32 KB)
    __shared__ float s_htab[32];      // 20-entry h table (padded)

    const int b    = blockIdx.x;      // batch index
    const int tile = blockIdx.y;      // which TILE_ROWS chunk of L
    const int tid  = threadIdx.x;

    if (tid < 32) s_htab[tid] = (tid < 20) ? h[tid] : 0.0f;
    __syncthreads();

    // Stage h[seq[b,:]] into smem. seq row = 32 KB, L2-resident across blocks.
    const int* seq_b = seq + b * L_DIM;
    for (int idx = tid; idx < L_DIM; idx += THREADS) {
        int s = seq_b[idx];
        s_hseq[idx] = s_htab[s];
    }

    // Scalars (broadcast loads; L2 hits). softplus via precise expf/log1pf.
    const float md     = (float)(*max_dist);
    const float r_peak = log1pf(expf(*r_half_raw));
    const float sigma  = log1pf(expf(*tau_hp_raw)) + 0.1f;
    // g = exp(-(d^2)/(2 sigma^2)) = 2^( d^2 * (-log2e / (2 sigma^2)) )
    const float nscale = -1.44269504088896340736f / (2.0f * sigma * sigma);
    const float thresh = md - 1e-4f;

    __syncthreads();

    const int warp = tid >> 5;
    const int lane = tid & 31;
    const int row0 = tile * TILE_ROWS;

    const float* rb = r     + ((size_t)b * L_DIM) * K_DIM;
    const int*   jb = j_idx + ((size_t)b * L_DIM) * K_DIM;

    #pragma unroll 4
    for (int it = 0; it < TILE_ROWS / WARPS; ++it) {
        const int i = row0 + it * WARPS + warp;   // row handled by this warp

        // lane covers k = 2*lane, 2*lane+1  (coalesced 256B per warp per array)
        const size_t base = (size_t)i * K_DIM + 2 * lane;
        const float2 rv = *(const float2*)(rb + base);
        const int2   jv = *(const int2*)(jb + base);

        // clamp j like the reference, gather h_j from smem
        const int j0 = min(max(jv.x, 0), L_DIM - 1);
        const int j1 = min(max(jv.y, 0), L_DIM - 1);
        const float hj0 = s_hseq[j0];
        const float hj1 = s_hseq[j1];

        const float d0 = fminf(rv.x, md) - r_peak;
        const float d1 = fminf(rv.y, md) - r_peak;
        const float t0 = d0 * d0 * nscale;
        const float t1 = d1 * d1 * nscale;

        float g0, g1;
        asm("ex2.approx.ftz.f32 %0, %1;" : "=f"(g0) : "f"(t0));
        asm("ex2.approx.ftz.f32 %0, %1;" : "=f"(g1) : "f"(t1));

        g0 = (rv.x < thresh) ? g0 : 0.0f;
        g1 = (rv.y < thresh) ? g1 : 0.0f;

        float acc = fmaf(hj0, g0, hj1 * g1);

        // warp reduction over the 64 k-terms
        #pragma unroll
        for (int off = 16; off; off >>= 1)
            acc += __shfl_xor_sync(0xffffffffu, acc, off);

        if (lane == 0)
            out[(size_t)b * L_DIM + i] = s_hseq[i] * acc;
    }
}

extern "C" void kernel_launch(void* const* d_in, const int* in_sizes, int n_in,
                              void* d_out, int out_size)
{
    // metadata order: seq, r, j_idx, h, r_half_raw, tau_hp_raw, max_dist
    const int*   seq        = (const int*)d_in[0];
    const float* r          = (const float*)d_in[1];
    const int*   j_idx      = (const int*)d_in[2];
    const float* h          = (const float*)d_in[3];
    const float* r_half_raw = (const float*)d_in[4];
    const float* tau_hp_raw = (const float*)d_in[5];
    const int*   max_dist   = (const int*)d_in[6];
    float*       out        = (float*)d_out;

    dim3 grid(B_DIM, L_DIM / TILE_ROWS);   // 32 x 64 = 2048 blocks
    hp_pairs_kernel<<<grid, THREADS>>>(seq, r, j_idx, h,
                                       r_half_raw, tau_hp_raw, max_dist, out);
}

// round 2
// speedup vs baseline: 1.3954x; 1.3954x over previous
#include <cuda_runtime.h>
#include <math.h>

// Problem shape (fixed by the dataset): B=32, L=8192, K=64, 20 amino acids.
#define B_DIM 32
#define L_DIM 8192
#define K_DIM 64
#define THREADS 256
#define WARPS (THREADS / 32)
#define UNROLL 4
#define TILE_ROWS 128            // rows of i per block; 2 macro-iters of 64 rows

// Precomputed h[seq[b,l]] table (1 MB, static device scratch — allowed).
__device__ float g_hseq[B_DIM * L_DIM];

__global__ void hseq_precompute(const int* __restrict__ seq,
                                const float* __restrict__ h)
{
    int idx = blockIdx.x * blockDim.x + threadIdx.x;
    if (idx < B_DIM * L_DIM) {
        int s = seq[idx];
        g_hseq[idx] = __ldg(h + s);
    }
}

__global__ __launch_bounds__(THREADS)
void hp_pairs_kernel(const float* __restrict__ r,
                     const int* __restrict__ j_idx,
                     const float* __restrict__ r_half_raw,
                     const float* __restrict__ tau_hp_raw,
                     const int* __restrict__ max_dist,
                     float* __restrict__ out)
{
    __shared__ float s_hseq[L_DIM];   // h[seq[b, :]] for this batch row (32 KB)

    const int b    = blockIdx.x;      // batch index
    const int tile = blockIdx.y;      // which TILE_ROWS chunk of L
    const int tid  = threadIdx.x;

    // Stage precomputed hseq row into smem: pure float4 copy, no dependency chain.
    {
        const float4* src = (const float4*)(g_hseq + b * L_DIM);
        float4*       dst = (float4*)s_hseq;
        #pragma unroll
        for (int it = 0; it < L_DIM / 4 / THREADS; ++it)
            dst[tid + it * THREADS] = src[tid + it * THREADS];
    }

    // Scalars (broadcast loads; L2 hits).
    const float md     = (float)(*max_dist);
    const float r_peak = log1pf(expf(*r_half_raw));
    const float sigma  = log1pf(expf(*tau_hp_raw)) + 0.1f;
    // g = exp(-d^2/(2 sigma^2)) = 2^( d^2 * (-log2e / (2 sigma^2)) )
    const float nscale = -1.44269504088896340736f / (2.0f * sigma * sigma);
    const float thresh = md - 1e-4f;

    __syncthreads();

    const int warp = tid >> 5;
    const int lane = tid & 31;
    const int half = lane >> 4;       // which of the warp's 2 rows
    const int l15  = lane & 15;       // k-chunk within row (4 floats each)
    const int row0 = tile * TILE_ROWS;

    const float* rb = r     + ((size_t)b * L_DIM) * K_DIM;
    const int*   jb = j_idx + ((size_t)b * L_DIM) * K_DIM;
    float*       ob = out   + (size_t)b * L_DIM;

    #pragma unroll
    for (int mi = 0; mi < TILE_ROWS / (WARPS * UNROLL * 2); ++mi) {
        // ---- batched load phase: 8 independent LDG.128 in flight ----
        float4 rv[UNROLL];
        int4   jv[UNROLL];
        int    rowA[UNROLL];
        #pragma unroll
        for (int u = 0; u < UNROLL; ++u) {
            int rr = row0 + ((mi * UNROLL + u) * WARPS + warp) * 2 + half;
            rowA[u] = rr;
            const size_t base = (size_t)rr * K_DIM + l15 * 4;
            rv[u] = *(const float4*)(rb + base);
            jv[u] = *(const int4*)(jb + base);
        }

        // ---- compute phase ----
        #pragma unroll
        for (int u = 0; u < UNROLL; ++u) {
            const int j0 = min(max(jv[u].x, 0), L_DIM - 1);
            const int j1 = min(max(jv[u].y, 0), L_DIM - 1);
            const int j2 = min(max(jv[u].z, 0), L_DIM - 1);
            const int j3 = min(max(jv[u].w, 0), L_DIM - 1);
            const float hj0 = s_hseq[j0];
            const float hj1 = s_hseq[j1];
            const float hj2 = s_hseq[j2];
            const float hj3 = s_hseq[j3];

            const float d0 = fminf(rv[u].x, md) - r_peak;
            const float d1 = fminf(rv[u].y, md) - r_peak;
            const float d2 = fminf(rv[u].z, md) - r_peak;
            const float d3 = fminf(rv[u].w, md) - r_peak;

            float g0, g1, g2, g3;
            asm("ex2.approx.ftz.f32 %0, %1;" : "=f"(g0) : "f"(d0 * d0 * nscale));
            asm("ex2.approx.ftz.f32 %0, %1;" : "=f"(g1) : "f"(d1 * d1 * nscale));
            asm("ex2.approx.ftz.f32 %0, %1;" : "=f"(g2) : "f"(d2 * d2 * nscale));
            asm("ex2.approx.ftz.f32 %0, %1;" : "=f"(g3) : "f"(d3 * d3 * nscale));

            g0 = (rv[u].x < thresh) ? g0 : 0.0f;
            g1 = (rv[u].y < thresh) ? g1 : 0.0f;
            g2 = (rv[u].z < thresh) ? g2 : 0.0f;
            g3 = (rv[u].w < thresh) ? g3 : 0.0f;

            float acc = fmaf(hj0, g0, hj1 * g1) + fmaf(hj2, g2, hj3 * g3);

            // reduce over the 16 lanes holding this row
            #pragma unroll
            for (int off = 8; off; off >>= 1)
                acc += __shfl_xor_sync(0xffffffffu, acc, off);

            if (l15 == 0)
                ob[rowA[u]] = s_hseq[rowA[u]] * acc;
        }
    }
}

extern "C" void kernel_launch(void* const* d_in, const int* in_sizes, int n_in,
                              void* d_out, int out_size)
{
    // metadata order: seq, r, j_idx, h, r_half_raw, tau_hp_raw, max_dist
    const int*   seq        = (const int*)d_in[0];
    const float* r          = (const float*)d_in[1];
    const int*   j_idx      = (const int*)d_in[2];
    const float* h          = (const float*)d_in[3];
    const float* r_half_raw = (const float*)d_in[4];
    const float* tau_hp_raw = (const float*)d_in[5];
    const int*   max_dist   = (const int*)d_in[6];
    float*       out        = (float*)d_out;

    hseq_precompute<<<(B_DIM * L_DIM + 255) / 256, 256>>>(seq, h);

    dim3 grid(B_DIM, L_DIM / TILE_ROWS);   // 32 x 64 = 2048 blocks
    hp_pairs_kernel<<<grid, THREADS>>>(r, j_idx,
                                       r_half_raw, tau_hp_raw, max_dist, out);
}